// round 15
// baseline (speedup 1.0000x reference)
#include <cuda_runtime.h>
#include <math.h>

#define BB 4
#define SS 4096
#define DD 1024
#define ND 4096                   // floats per (b,s)
#define ND4 1024                  // float4 per (b,s)
#define D4 256                    // float4 per stream row
#define NCOLS 24
#define SCHUNKS 32
#define SPERCHUNK 128
#define CB 4                      // col-blocks (1024 floats each)

// Scratch (allocation-free rule: __device__ globals)
__device__ float    g_partial[BB][SCHUNKS][ND];    // 2 MB
__device__ float    g_dpart[BB][CB][NCOLS];        // gate dot partials
__device__ float    g_ssp[BB][CB];                 // sum-of-squares partials
__device__ float    g_gates[BB][24];               // pre[4], post[4], P[16]
__device__ unsigned g_rcnt[BB][CB];                // per-(b,colblk) counters
__device__ unsigned g_gcnt;                        // finalize counter

// ---------------------------------------------------------------------------
// Kernel 1: column partial sums + gate epilogue, REGISTER-CAPPED.
// __launch_bounds__(256, 6) caps regs at ~42 so the streaming Phase A keeps
// 6+ blocks/SM occupancy (R12's failure was reg bloat from the epilogue
// de-occupying the stream loop). The epilogue may spill; it is ~3us of work
// on 16 blocks and doesn't matter.
// Phase A: per-(b,chunk,colblk) partial sums, s DESCENDING (head half of each
//   chunk stays L2-resident for mix's hot half). Evict-normal loads.
// Phase B: last-done block per (b,colblk) computes gate dot partials for its
//   1024 columns (g_partial L2-hot).
// Phase C: last of the 16 runs sigmoid/normalize/Sinkhorn.
// All "last-block" results are pure functions of fully-written data.
// ---------------------------------------------------------------------------
__global__ void __launch_bounds__(256, 6)
k_reduce(const float4* __restrict__ H4,
         const float* __restrict__ phi,
         const float* __restrict__ pre_base,
         const float* __restrict__ post_base,
         const float* __restrict__ res_base,
         const float* __restrict__ a_pre,
         const float* __restrict__ a_post,
         const float* __restrict__ a_res) {
    const int b      = blockIdx.z;
    const int chunk  = blockIdx.y;
    const int colblk = blockIdx.x;
    const int t      = threadIdx.x;
    const int col4   = colblk * 256 + t;

    // ---- Phase A: chunk partial sum (descending s) ----
    {
        const float4* base =
            H4 + ((size_t)b * SS + (size_t)chunk * SPERCHUNK) * ND4 + col4;
        float4 acc = make_float4(0.f, 0.f, 0.f, 0.f);
#pragma unroll 16
        for (int s = SPERCHUNK - 1; s >= 0; s--) {
            const float4 v = base[(size_t)s * ND4];
            acc.x += v.x; acc.y += v.y; acc.z += v.z; acc.w += v.w;
        }
        ((float4*)&g_partial[b][chunk][0])[col4] = acc;
    }
    __threadfence();              // publish this block's slice
    __syncthreads();

    __shared__ int is_last;
    if (t == 0) {
        const unsigned old = atomicAdd(&g_rcnt[b][colblk], 1u);
        is_last = (old == (unsigned)(SCHUNKS - 1));
        if (is_last) {
            atomicExch(&g_rcnt[b][colblk], 0u);   // self-reset (graph replay)
            __threadfence();                       // acquire peers' slices
        }
    }
    __syncthreads();
    if (!is_last) return;

    // ---- Phase B: gate partials for this (b, colblk)'s 1024 columns ----
    const int lane = t & 31;
    const int warp = t >> 5;                  // 0..7

    float acc24[NCOLS];
#pragma unroll
    for (int j = 0; j < NCOLS; j++) acc24[j] = 0.0f;
    float ss = 0.0f;

#pragma unroll
    for (int r = 0; r < 4; r++) {
        const int col = colblk * 1024 + r * 256 + t;
        float x = 0.0f;
#pragma unroll
        for (int ch = 0; ch < SCHUNKS; ch++) x += g_partial[b][ch][col];
        x *= (1.0f / (float)SS);
        ss += x * x;
        const float* ph = phi + (size_t)col * NCOLS;
#pragma unroll
        for (int j = 0; j < NCOLS; j++) acc24[j] += x * ph[j];
    }

#pragma unroll
    for (int o = 16; o > 0; o >>= 1) {
        ss += __shfl_down_sync(0xffffffffu, ss, o);
#pragma unroll
        for (int j = 0; j < NCOLS; j++)
            acc24[j] += __shfl_down_sync(0xffffffffu, acc24[j], o);
    }

    __shared__ float sred[8][NCOLS];
    __shared__ float sss[8];
    if (lane == 0) {
#pragma unroll
        for (int j = 0; j < NCOLS; j++) sred[warp][j] = acc24[j];
        sss[warp] = ss;
    }
    __syncthreads();

    if (t < NCOLS) {
        float v = 0.0f;
#pragma unroll
        for (int w = 0; w < 8; w++) v += sred[w][t];
        g_dpart[b][colblk][t] = v;
    } else if (t == NCOLS) {
        float v = 0.0f;
#pragma unroll
        for (int w = 0; w < 8; w++) v += sss[w];
        g_ssp[b][colblk] = v;
    }
    if (t <= NCOLS) __threadfence();
    __syncthreads();

    __shared__ int is_final;
    if (t == 0) {
        const unsigned old = atomicAdd(&g_gcnt, 1u);
        is_final = (old == (unsigned)(BB * CB - 1));
        if (is_final) {
            atomicExch(&g_gcnt, 0u);               // self-reset
            __threadfence();                        // acquire all partials
        }
    }
    __syncthreads();
    if (!is_final) return;

    // ---- Phase C: finalize gates (4 warps = 4 batches) ----
    if (t < 128) {
        const int bb = t >> 5;
        const int ln = t & 31;

        __shared__ float sdelta[BB][NCOLS];

        float invrms = 0.0f;
        if (ln == 0) {
            float ssum = 0.0f;
#pragma unroll
            for (int k = 0; k < CB; k++) ssum += g_ssp[bb][k];
            invrms = 1.0f / sqrtf(ssum * (1.0f / (float)ND) + 1e-6f);
        }
        invrms = __shfl_sync(0xffffffffu, invrms, 0);

        if (ln < NCOLS) {
            float v = 0.0f;
#pragma unroll
            for (int k = 0; k < CB; k++) v += g_dpart[bb][k][ln];
            sdelta[bb][ln] = v * invrms;
        }
        __syncwarp();

        if (ln == 0) {
            const float ap  = *a_pre;
            const float apo = *a_post;
            const float ar  = *a_res;

            float pre[4];
            float psum = 0.0f;
#pragma unroll
            for (int k = 0; k < 4; k++) {
                pre[k] = 1.0f / (1.0f + expf(-(pre_base[k] + ap * sdelta[bb][k])));
                psum += pre[k];
            }
            const float pinv = 1.0f / (psum + 1e-8f);
#pragma unroll
            for (int k = 0; k < 4; k++) g_gates[bb][k] = pre[k] * pinv;

#pragma unroll
            for (int k = 0; k < 4; k++)
                g_gates[bb][4 + k] =
                    1.0f / (1.0f + expf(-(post_base[k] + apo * sdelta[bb][4 + k])));

            float P[16];
#pragma unroll
            for (int q = 0; q < 16; q++)
                P[q] = expf(res_base[q] + ar * sdelta[bb][8 + q]);
            for (int it = 0; it < 20; it++) {
#pragma unroll
                for (int i = 0; i < 4; i++) {
                    const float rs = P[i*4+0] + P[i*4+1] + P[i*4+2] + P[i*4+3];
                    const float inv = 1.0f / (rs + 1e-6f);
                    P[i*4+0] *= inv; P[i*4+1] *= inv; P[i*4+2] *= inv; P[i*4+3] *= inv;
                }
#pragma unroll
                for (int j = 0; j < 4; j++) {
                    const float cs = P[0*4+j] + P[1*4+j] + P[2*4+j] + P[3*4+j];
                    const float inv = 1.0f / (cs + 1e-6f);
                    P[0*4+j] *= inv; P[1*4+j] *= inv; P[2*4+j] *= inv; P[3*4+j] *= inv;
                }
            }
#pragma unroll
            for (int q = 0; q < 16; q++) g_gates[bb][8 + q] = P[q];
        }
    }
}

// ---------------------------------------------------------------------------
// Kernel 2: streaming mix (EXACT verified R10/R13 form, 6.47 TB/s). One block
// per TWO rows; hot halves at low blockIdx. Loads .cs, stores .cs.
// ---------------------------------------------------------------------------
__global__ void __launch_bounds__(256) k_mix(const float* __restrict__ H,
                                             const float* __restrict__ bo,
                                             float* __restrict__ out) {
    const int idx   = blockIdx.x;            // 0..8191
    const int half  = idx >> 12;             // 0 = hot halves, 1 = cold
    const int rest  = idx & 4095;
    const int pair  = rest & 31;
    const int chunk = (rest >> 5) & 31;
    const int b     = rest >> 10;
    const int bs0   = b * SS + chunk * SPERCHUNK + half * 64 + pair * 2;
    const int bs1   = bs0 + 1;
    const int d4    = threadIdx.x;

    __shared__ float g[24];
    if (threadIdx.x < 24) g[threadIdx.x] = g_gates[b][threadIdx.x];

    const float4* hA = (const float4*)(H + (size_t)bs0 * ND);
    const float4* hB = (const float4*)(H + (size_t)bs1 * ND);

    const float4 a0 = __ldcs(hA + 0 * D4 + d4);
    const float4 a1 = __ldcs(hA + 1 * D4 + d4);
    const float4 a2 = __ldcs(hA + 2 * D4 + d4);
    const float4 a3 = __ldcs(hA + 3 * D4 + d4);
    const float4 av = __ldcs((const float4*)(bo + (size_t)bs0 * DD) + d4);
    const float4 b0 = __ldcs(hB + 0 * D4 + d4);
    const float4 b1 = __ldcs(hB + 1 * D4 + d4);
    const float4 b2 = __ldcs(hB + 2 * D4 + d4);
    const float4 b3 = __ldcs(hB + 3 * D4 + d4);
    const float4 bv = __ldcs((const float4*)(bo + (size_t)bs1 * DD) + d4);

    __syncthreads();

    float4* oA = (float4*)(out + (size_t)bs0 * 5 * DD);
    float4* oB = (float4*)(out + (size_t)bs1 * 5 * DD);

    {
        float4 o;
        o.x = g[0]*a0.x + g[1]*a1.x + g[2]*a2.x + g[3]*a3.x;
        o.y = g[0]*a0.y + g[1]*a1.y + g[2]*a2.y + g[3]*a3.y;
        o.z = g[0]*a0.z + g[1]*a1.z + g[2]*a2.z + g[3]*a3.z;
        o.w = g[0]*a0.w + g[1]*a1.w + g[2]*a2.w + g[3]*a3.w;
        __stcs(oA + d4, o);
        o.x = g[0]*b0.x + g[1]*b1.x + g[2]*b2.x + g[3]*b3.x;
        o.y = g[0]*b0.y + g[1]*b1.y + g[2]*b2.y + g[3]*b3.y;
        o.z = g[0]*b0.z + g[1]*b1.z + g[2]*b2.z + g[3]*b3.z;
        o.w = g[0]*b0.w + g[1]*b1.w + g[2]*b2.w + g[3]*b3.w;
        __stcs(oB + d4, o);
    }

#pragma unroll
    for (int i = 0; i < 4; i++) {
        const float r0 = g[8 + i * 4 + 0];
        const float r1 = g[8 + i * 4 + 1];
        const float r2 = g[8 + i * 4 + 2];
        const float r3 = g[8 + i * 4 + 3];
        const float p  = g[4 + i];
        float4 o;
        o.x = r0*a0.x + r1*a1.x + r2*a2.x + r3*a3.x + p*av.x;
        o.y = r0*a0.y + r1*a1.y + r2*a2.y + r3*a3.y + p*av.y;
        o.z = r0*a0.z + r1*a1.z + r2*a2.z + r3*a3.z + p*av.z;
        o.w = r0*a0.w + r1*a1.w + r2*a2.w + r3*a3.w + p*av.w;
        __stcs(oA + (1 + i) * D4 + d4, o);
        o.x = r0*b0.x + r1*b1.x + r2*b2.x + r3*b3.x + p*bv.x;
        o.y = r0*b0.y + r1*b1.y + r2*b2.y + r3*b3.y + p*bv.y;
        o.z = r0*b0.z + r1*b1.z + r2*b2.z + r3*b3.z + p*bv.z;
        o.w = r0*b0.w + r1*b1.w + r2*b2.w + r3*b3.w + p*bv.w;
        __stcs(oB + (1 + i) * D4 + d4, o);
    }
}

// ---------------------------------------------------------------------------
extern "C" void kernel_launch(void* const* d_in, const int* in_sizes, int n_in,
                              void* d_out, int out_size) {
    const float* H         = (const float*)d_in[0];
    const float* branch_o  = (const float*)d_in[1];
    const float* phi       = (const float*)d_in[2];
    const float* pre_base  = (const float*)d_in[3];
    const float* post_base = (const float*)d_in[4];
    const float* res_base  = (const float*)d_in[5];
    const float* a_pre     = (const float*)d_in[6];
    const float* a_post    = (const float*)d_in[7];
    const float* a_res     = (const float*)d_in[8];
    float* out = (float*)d_out;

    dim3 g1(CB, SCHUNKS, BB);
    k_reduce<<<g1, 256>>>((const float4*)H, phi, pre_base, post_base, res_base,
                          a_pre, a_post, a_res);
    const int mix_grid = (BB * SS) / 2;       // 8192 blocks, 2 rows each
    k_mix<<<mix_grid, 256>>>(H, branch_o, out);
}

// round 16
// speedup vs baseline: 1.0712x; 1.0712x over previous
#include <cuda_runtime.h>
#include <math.h>

#define BB 4
#define SS 4096
#define DD 1024
#define ND 4096                   // floats per (b,s)
#define ND4 1024                  // float4 per (b,s)
#define D4 256                    // float4 per stream row
#define NCOLS 24
#define SCHUNKS 64                // 64-row chunks -> 1024 reduce blocks
#define SPERCHUNK 64              //   (98.9% wave efficiency on 148 SMs)
#define GA 16                     // gate col-blocks per batch (64 total)

// Scratch (allocation-free rule: __device__ globals)
__device__ float    g_partial[BB][SCHUNKS][ND];    // 4 MB
__device__ float    g_dpart[BB][GA][NCOLS];
__device__ float    g_ssp[BB][GA];
__device__ float    g_gates[BB][24];               // pre[4], post[4], P[16]
__device__ unsigned g_gcnt;                        // gate completion counter

// ---------------------------------------------------------------------------
// Kernel 1: column partial sums over S, per 64-row chunk, s DESCENDING so the
// head (s_local 0..~31) of every chunk is L2-resident at kernel end --
// exactly the quarters k_mix's hot pass consumes first. Evict-normal loads.
// grid (4, 64, 4) x 256 = 1024 blocks: 148-SM wave efficiency 98.9% (vs 86.5%
// at 512 blocks -- the R10 reduce's tail imbalance).
// ---------------------------------------------------------------------------
__global__ void __launch_bounds__(256) k_reduce(const float4* __restrict__ H4) {
    const int b     = blockIdx.z;
    const int chunk = blockIdx.y;
    const int col4  = blockIdx.x * 256 + threadIdx.x;
    const float4* base = H4 + ((size_t)b * SS + (size_t)chunk * SPERCHUNK) * ND4 + col4;
    float4 acc = make_float4(0.f, 0.f, 0.f, 0.f);
#pragma unroll 16
    for (int s = SPERCHUNK - 1; s >= 0; s--) {
        const float4 v = base[(size_t)s * ND4];
        acc.x += v.x; acc.y += v.y; acc.z += v.z; acc.w += v.w;
    }
    ((float4*)&g_partial[b][chunk][0])[col4] = acc;
}

// ---------------------------------------------------------------------------
// Kernel 2: fused gate reduction + finalize (verified R10 form). 64 blocks x
// 256 threads; last-done block (order-independent result) runs Sinkhorn.
// ---------------------------------------------------------------------------
__global__ void __launch_bounds__(256) k_gates(const float* __restrict__ phi,
                                               const float* __restrict__ pre_base,
                                               const float* __restrict__ post_base,
                                               const float* __restrict__ res_base,
                                               const float* __restrict__ a_pre,
                                               const float* __restrict__ a_post,
                                               const float* __restrict__ a_res) {
    const int b    = blockIdx.x >> 4;
    const int g    = blockIdx.x & 15;
    const int t    = threadIdx.x;
    const int lane = t & 31;
    const int warp = t >> 5;                 // 0..7
    const int col  = g * 256 + t;

    float x = 0.0f;
#pragma unroll
    for (int ch = 0; ch < SCHUNKS; ch++) x += g_partial[b][ch][col];
    x *= (1.0f / (float)SS);

    float acc24[NCOLS];
    const float* ph = phi + (size_t)col * NCOLS;
#pragma unroll
    for (int j = 0; j < NCOLS; j++) acc24[j] = x * ph[j];
    float ss = x * x;

#pragma unroll
    for (int o = 16; o > 0; o >>= 1) {
        ss += __shfl_down_sync(0xffffffffu, ss, o);
#pragma unroll
        for (int j = 0; j < NCOLS; j++)
            acc24[j] += __shfl_down_sync(0xffffffffu, acc24[j], o);
    }

    __shared__ float sred[8][NCOLS];
    __shared__ float sss[8];
    if (lane == 0) {
#pragma unroll
        for (int j = 0; j < NCOLS; j++) sred[warp][j] = acc24[j];
        sss[warp] = ss;
    }
    __syncthreads();

    if (t < NCOLS) {
        float v = 0.0f;
#pragma unroll
        for (int w = 0; w < 8; w++) v += sred[w][t];
        g_dpart[b][g][t] = v;
    } else if (t == NCOLS) {
        float v = 0.0f;
#pragma unroll
        for (int w = 0; w < 8; w++) v += sss[w];
        g_ssp[b][g] = v;
    }
    if (t <= NCOLS) __threadfence();
    __syncthreads();

    __shared__ int is_last;
    if (t == 0) {
        const unsigned old = atomicAdd(&g_gcnt, 1u);
        is_last = (old == (unsigned)(BB * GA - 1));
        if (is_last) atomicExch(&g_gcnt, 0u);    // self-reset for graph replay
        if (is_last) __threadfence();
    }
    __syncthreads();
    if (!is_last) return;

    if (t < 128) {
        const int bb = t >> 5;
        const int ln = t & 31;

        __shared__ float sdelta[BB][NCOLS];

        float invrms = 0.0f;
        if (ln == 0) {
            float ssum = 0.0f;
#pragma unroll
            for (int k = 0; k < GA; k++) ssum += g_ssp[bb][k];
            invrms = 1.0f / sqrtf(ssum * (1.0f / (float)ND) + 1e-6f);
        }
        invrms = __shfl_sync(0xffffffffu, invrms, 0);

        if (ln < NCOLS) {
            float v = 0.0f;
#pragma unroll
            for (int k = 0; k < GA; k++) v += g_dpart[bb][k][ln];
            sdelta[bb][ln] = v * invrms;
        }
        __syncwarp();

        if (ln == 0) {
            const float ap  = *a_pre;
            const float apo = *a_post;
            const float ar  = *a_res;

            float pre[4];
            float psum = 0.0f;
#pragma unroll
            for (int k = 0; k < 4; k++) {
                pre[k] = 1.0f / (1.0f + expf(-(pre_base[k] + ap * sdelta[bb][k])));
                psum += pre[k];
            }
            const float pinv = 1.0f / (psum + 1e-8f);
#pragma unroll
            for (int k = 0; k < 4; k++) g_gates[bb][k] = pre[k] * pinv;

#pragma unroll
            for (int k = 0; k < 4; k++)
                g_gates[bb][4 + k] =
                    1.0f / (1.0f + expf(-(post_base[k] + apo * sdelta[bb][4 + k])));

            float P[16];
#pragma unroll
            for (int q = 0; q < 16; q++)
                P[q] = expf(res_base[q] + ar * sdelta[bb][8 + q]);
            for (int it = 0; it < 20; it++) {
#pragma unroll
                for (int i = 0; i < 4; i++) {
                    const float rs = P[i*4+0] + P[i*4+1] + P[i*4+2] + P[i*4+3];
                    const float inv = 1.0f / (rs + 1e-6f);
                    P[i*4+0] *= inv; P[i*4+1] *= inv; P[i*4+2] *= inv; P[i*4+3] *= inv;
                }
#pragma unroll
                for (int j = 0; j < 4; j++) {
                    const float cs = P[0*4+j] + P[1*4+j] + P[2*4+j] + P[3*4+j];
                    const float inv = 1.0f / (cs + 1e-6f);
                    P[0*4+j] *= inv; P[1*4+j] *= inv; P[2*4+j] *= inv; P[3*4+j] *= inv;
                }
            }
#pragma unroll
            for (int q = 0; q < 16; q++) g_gates[bb][8 + q] = P[q];
        }
    }
}

// ---------------------------------------------------------------------------
// Kernel 3: streaming mix (verified 6.47-6.65 TB/s form). One block per TWO
// rows. Hot pass (low blockIdx) = quarters 0 & 2 of each 128-row group = the
// heads of the 64-row reduce chunks that are L2-resident; cold pass follows.
// Loads .cs, stores .cs.
// ---------------------------------------------------------------------------
__global__ void __launch_bounds__(256) k_mix(const float* __restrict__ H,
                                             const float* __restrict__ bo,
                                             float* __restrict__ out) {
    const int idx   = blockIdx.x;            // 0..8191
    const int half  = idx >> 12;             // 0 = hot quarters, 1 = cold
    const int rest  = idx & 4095;
    const int pair  = rest & 31;             // 32 pairs per 128-row group
    const int group = (rest >> 5) & 31;      // 128-row groups
    const int b     = rest >> 10;
    // quarter q: half=0 -> {0,2}, half=1 -> {1,3}
    const int q     = ((pair >> 4) << 1) + half;
    const int bs0   = b * SS + group * 128 + q * 32 + (pair & 15) * 2;
    const int bs1   = bs0 + 1;
    const int d4    = threadIdx.x;

    __shared__ float g[24];
    if (threadIdx.x < 24) g[threadIdx.x] = g_gates[b][threadIdx.x];

    const float4* hA = (const float4*)(H + (size_t)bs0 * ND);
    const float4* hB = (const float4*)(H + (size_t)bs1 * ND);

    const float4 a0 = __ldcs(hA + 0 * D4 + d4);
    const float4 a1 = __ldcs(hA + 1 * D4 + d4);
    const float4 a2 = __ldcs(hA + 2 * D4 + d4);
    const float4 a3 = __ldcs(hA + 3 * D4 + d4);
    const float4 av = __ldcs((const float4*)(bo + (size_t)bs0 * DD) + d4);
    const float4 b0 = __ldcs(hB + 0 * D4 + d4);
    const float4 b1 = __ldcs(hB + 1 * D4 + d4);
    const float4 b2 = __ldcs(hB + 2 * D4 + d4);
    const float4 b3 = __ldcs(hB + 3 * D4 + d4);
    const float4 bv = __ldcs((const float4*)(bo + (size_t)bs1 * DD) + d4);

    __syncthreads();

    float4* oA = (float4*)(out + (size_t)bs0 * 5 * DD);
    float4* oB = (float4*)(out + (size_t)bs1 * 5 * DD);

    {
        float4 o;
        o.x = g[0]*a0.x + g[1]*a1.x + g[2]*a2.x + g[3]*a3.x;
        o.y = g[0]*a0.y + g[1]*a1.y + g[2]*a2.y + g[3]*a3.y;
        o.z = g[0]*a0.z + g[1]*a1.z + g[2]*a2.z + g[3]*a3.z;
        o.w = g[0]*a0.w + g[1]*a1.w + g[2]*a2.w + g[3]*a3.w;
        __stcs(oA + d4, o);
        o.x = g[0]*b0.x + g[1]*b1.x + g[2]*b2.x + g[3]*b3.x;
        o.y = g[0]*b0.y + g[1]*b1.y + g[2]*b2.y + g[3]*b3.y;
        o.z = g[0]*b0.z + g[1]*b1.z + g[2]*b2.z + g[3]*b3.z;
        o.w = g[0]*b0.w + g[1]*b1.w + g[2]*b2.w + g[3]*b3.w;
        __stcs(oB + d4, o);
    }

#pragma unroll
    for (int i = 0; i < 4; i++) {
        const float r0 = g[8 + i * 4 + 0];
        const float r1 = g[8 + i * 4 + 1];
        const float r2 = g[8 + i * 4 + 2];
        const float r3 = g[8 + i * 4 + 3];
        const float p  = g[4 + i];
        float4 o;
        o.x = r0*a0.x + r1*a1.x + r2*a2.x + r3*a3.x + p*av.x;
        o.y = r0*a0.y + r1*a1.y + r2*a2.y + r3*a3.y + p*av.y;
        o.z = r0*a0.z + r1*a1.z + r2*a2.z + r3*a3.z + p*av.z;
        o.w = r0*a0.w + r1*a1.w + r2*a2.w + r3*a3.w + p*av.w;
        __stcs(oA + (1 + i) * D4 + d4, o);
        o.x = r0*b0.x + r1*b1.x + r2*b2.x + r3*b3.x + p*bv.x;
        o.y = r0*b0.y + r1*b1.y + r2*b2.y + r3*b3.y + p*bv.y;
        o.z = r0*b0.z + r1*b1.z + r2*b2.z + r3*b3.z + p*bv.z;
        o.w = r0*b0.w + r1*b1.w + r2*b2.w + r3*b3.w + p*bv.w;
        __stcs(oB + (1 + i) * D4 + d4, o);
    }
}

// ---------------------------------------------------------------------------
extern "C" void kernel_launch(void* const* d_in, const int* in_sizes, int n_in,
                              void* d_out, int out_size) {
    const float* H         = (const float*)d_in[0];
    const float* branch_o  = (const float*)d_in[1];
    const float* phi       = (const float*)d_in[2];
    const float* pre_base  = (const float*)d_in[3];
    const float* post_base = (const float*)d_in[4];
    const float* res_base  = (const float*)d_in[5];
    const float* a_pre     = (const float*)d_in[6];
    const float* a_post    = (const float*)d_in[7];
    const float* a_res     = (const float*)d_in[8];
    float* out = (float*)d_out;

    dim3 g1(ND4 / 256, SCHUNKS, BB);          // (4, 64, 4) = 1024 blocks
    k_reduce<<<g1, 256>>>((const float4*)H);
    k_gates<<<BB * GA, 256>>>(phi, pre_base, post_base, res_base,
                              a_pre, a_post, a_res);
    const int mix_grid = (BB * SS) / 2;       // 8192 blocks, 2 rows each
    k_mix<<<mix_grid, 256>>>(H, branch_o, out);
}